// round 3
// baseline (speedup 1.0000x reference)
#include <cuda_runtime.h>
#include <cstdint>

constexpr int B_ = 8;     // batch
constexpr int Q_ = 128;   // queries
constexpr int K_ = 1024;  // keys
constexpr int D_ = 512;   // qk feature dim
constexpr int H_ = 256;   // hidden
constexpr int V_ = 512;   // value dim
constexpr int MK = B_ * K_;   // 8192 rows of kproj

// Scratch (no cudaMalloc allowed)
__device__ float g_qproj [B_ * Q_ * H_];   // [B*Q][H]   1 MB
__device__ float g_kprojT[H_ * B_ * K_];   // [H][B*K]   8 MB (transposed)

__device__ __forceinline__ float tanh_fast(float x) {
    float y;
    asm("tanh.approx.f32 %0, %1;" : "=f"(y) : "f"(x));
    return y;
}
__device__ __forceinline__ unsigned long long pack2(float lo, float hi) {
    unsigned long long r;
    asm("mov.b64 %0, {%1, %2};" : "=l"(r) : "f"(lo), "f"(hi));
    return r;
}
__device__ __forceinline__ float2 unpack2(unsigned long long v) {
    float2 r;
    asm("mov.b64 {%0, %1}, %2;" : "=f"(r.x), "=f"(r.y) : "l"(v));
    return r;
}
__device__ __forceinline__ unsigned long long fma2(unsigned long long a,
                                                   unsigned long long b,
                                                   unsigned long long c) {
    unsigned long long d;
    asm("fma.rn.f32x2 %0, %1, %2, %3;" : "=l"(d) : "l"(a), "l"(b), "l"(c));
    return d;
}

// ----------------------------------------------------------------------------
// Merged projection GEMM (unchanged from round 2).
//   blockIdx.y <  16 : qproj tile  -> g_qproj  [B*Q=1024][H]
//   blockIdx.y >= 16 : kproj tile  -> g_kprojT [H][B*K=8192] (transposed)
// ----------------------------------------------------------------------------
__global__ __launch_bounds__(128)
void proj_gemm(const float* __restrict__ queries, const float* __restrict__ keys,
               const float* __restrict__ Wq, const float* __restrict__ Wk)
{
    __shared__ float As[16][68];
    __shared__ float Bs[16][64];

    const int tid = threadIdx.x;
    const bool isQ = (blockIdx.y < 16);
    const float* A;
    const float* W;
    long long row0;
    if (isQ) { A = queries; W = Wq; row0 = (long long)blockIdx.y * 64; }
    else     { A = keys;    W = Wk; row0 = (long long)(blockIdx.y - 16) * 64; }
    const int col0 = blockIdx.x * 64;

    const int r0 = (tid >> 4) * 8;
    const int tn = (tid & 15) * 4;

    unsigned long long acc[8][2];
    #pragma unroll
    for (int i = 0; i < 8; i++) { acc[i][0] = 0ull; acc[i][1] = 0ull; }

    const int l0 = tid * 2;
    for (int kb = 0; kb < D_; kb += 16) {
        #pragma unroll
        for (int u = 0; u < 2; u++) {
            int l = l0 + u;
            int arow = l >> 2, ac4 = (l & 3) * 4;
            float4 av = *(const float4*)(A + (row0 + arow) * D_ + kb + ac4);
            As[ac4 + 0][arow] = av.x;
            As[ac4 + 1][arow] = av.y;
            As[ac4 + 2][arow] = av.z;
            As[ac4 + 3][arow] = av.w;
            int brow = l >> 4, bc4 = (l & 15) * 4;
            *(float4*)&Bs[brow][bc4] =
                *(const float4*)(W + (long long)(kb + brow) * H_ + col0 + bc4);
        }
        __syncthreads();

        #pragma unroll
        for (int kk = 0; kk < 16; kk++) {
            float4 alo = *(const float4*)&As[kk][r0];
            float4 ahi = *(const float4*)&As[kk][r0 + 4];
            float4 bq  = *(const float4*)&Bs[kk][tn];
            unsigned long long b01 = pack2(bq.x, bq.y);
            unsigned long long b23 = pack2(bq.z, bq.w);
            float a[8] = {alo.x, alo.y, alo.z, alo.w, ahi.x, ahi.y, ahi.z, ahi.w};
            #pragma unroll
            for (int ii = 0; ii < 8; ii++) {
                unsigned long long a2 = pack2(a[ii], a[ii]);
                acc[ii][0] = fma2(a2, b01, acc[ii][0]);
                acc[ii][1] = fma2(a2, b23, acc[ii][1]);
            }
        }
        __syncthreads();
    }

    if (isQ) {
        #pragma unroll
        for (int ii = 0; ii < 8; ii++) {
            float2 lo = unpack2(acc[ii][0]);
            float2 hi = unpack2(acc[ii][1]);
            float4 o = make_float4(lo.x, lo.y, hi.x, hi.y);
            *(float4*)(g_qproj + (row0 + r0 + ii) * H_ + col0 + tn) = o;
        }
    } else {
        float vals[8][4];
        #pragma unroll
        for (int ii = 0; ii < 8; ii++) {
            float2 lo = unpack2(acc[ii][0]);
            float2 hi = unpack2(acc[ii][1]);
            vals[ii][0] = lo.x; vals[ii][1] = lo.y;
            vals[ii][2] = hi.x; vals[ii][3] = hi.y;
        }
        #pragma unroll
        for (int jj = 0; jj < 4; jj++) {
            long long n = col0 + tn + jj;
            float4 o0 = make_float4(vals[0][jj], vals[1][jj], vals[2][jj], vals[3][jj]);
            float4 o1 = make_float4(vals[4][jj], vals[5][jj], vals[6][jj], vals[7][jj]);
            *(float4*)(g_kprojT + n * MK + row0 + r0)     = o0;
            *(float4*)(g_kprojT + n * MK + row0 + r0 + 4) = o1;
        }
    }
}

// ----------------------------------------------------------------------------
// Fused: masked tanh-scores + softmax + attn@values.
// Block = (b, q-tile of 4), 256 threads. Thread owns k = kpass*256 + tid.
// kprojT tiles [16 h][256 k] staged via coalesced bulk copy into smem;
// the tanh loop reads only smem (conflict-free) -> no long-scoreboard stalls.
// ----------------------------------------------------------------------------
__global__ __launch_bounds__(256)
void fused_attn(const float* __restrict__ wv, const int* __restrict__ vlens,
                const float* __restrict__ values, float* __restrict__ out)
{
    constexpr int QT = 4;
    constexpr int HC = 16;                 // h-chunk size
    __shared__ float s_tile[HC][256];      // 16 KB staged kproj tile
    __shared__ float s_sc[QT][K_];         // 16 KB scores / exp
    __shared__ float s_q[QT][H_];          // 4 KB
    __shared__ float s_wv[H_];             // 1 KB
    __shared__ float s_red[8];

    const int b    = blockIdx.y;
    const int q0   = blockIdx.x * QT;
    const int tid  = threadIdx.x;
    const int lane = tid & 31;
    const int wid  = tid >> 5;
    const int vlen = vlens[b];

    for (int i = tid; i < QT * H_; i += 256)
        s_q[i >> 8][i & 255] = g_qproj[(long long)(b * Q_ + q0 + (i >> 8)) * H_ + (i & 255)];
    for (int i = tid; i < H_; i += 256) s_wv[i] = wv[i];
    __syncthreads();

    // ---- scores (masked per 256-wide k pass, block-uniform skip) ----
    for (int kp = 0; kp < K_ / 256; kp++) {
        if (kp * 256 >= vlen) break;       // uniform across block
        float a0 = 0.f, a1 = 0.f, a2 = 0.f, a3 = 0.f;

        for (int hc = 0; hc < H_ / HC; hc++) {
            // stage [HC][256] tile: 1024 float4, 4 per thread, coalesced over k
            #pragma unroll
            for (int i = 0; i < 4; i++) {
                int idx = i * 256 + tid;
                int h = idx >> 6;              // 0..15
                int c4 = (idx & 63) << 2;      // 0..252
                float4 v = *(const float4*)(g_kprojT +
                    (long long)(hc * HC + h) * MK + b * K_ + kp * 256 + c4);
                *(float4*)&s_tile[h][c4] = v;
            }
            __syncthreads();

            #pragma unroll
            for (int hh = 0; hh < HC; hh++) {
                int h = hc * HC + hh;
                float kv = s_tile[hh][tid];
                float w  = s_wv[h];
                a0 = fmaf(tanh_fast(s_q[0][h] + kv), w, a0);
                a1 = fmaf(tanh_fast(s_q[1][h] + kv), w, a1);
                a2 = fmaf(tanh_fast(s_q[2][h] + kv), w, a2);
                a3 = fmaf(tanh_fast(s_q[3][h] + kv), w, a3);
            }
            __syncthreads();
        }
        int k = kp * 256 + tid;
        s_sc[0][k] = a0; s_sc[1][k] = a1; s_sc[2][k] = a2; s_sc[3][k] = a3;
    }
    __syncthreads();

    // ---- masked softmax (unnormalized exp in smem, inv in regs) ----
    float inv[QT];
    for (int j = 0; j < QT; j++) {
        float m = -3.4e38f;
        for (int k = tid; k < vlen; k += 256) m = fmaxf(m, s_sc[j][k]);
        #pragma unroll
        for (int off = 16; off; off >>= 1)
            m = fmaxf(m, __shfl_xor_sync(0xffffffffu, m, off));
        if (lane == 0) s_red[wid] = m;
        __syncthreads();
        float mm = s_red[0];
        #pragma unroll
        for (int w = 1; w < 8; w++) mm = fmaxf(mm, s_red[w]);
        __syncthreads();

        float s = 0.f;
        for (int k = tid; k < vlen; k += 256) {
            float e = __expf(s_sc[j][k] - mm);
            s_sc[j][k] = e;
            s += e;
        }
        #pragma unroll
        for (int off = 16; off; off >>= 1)
            s += __shfl_xor_sync(0xffffffffu, s, off);
        if (lane == 0) s_red[wid] = s;
        __syncthreads();
        float ssum = 0.f;
        #pragma unroll
        for (int w = 0; w < 8; w++) ssum += s_red[w];
        inv[j] = 1.0f / ssum;
        __syncthreads();
    }

    // ---- AV: out[j][v] = inv[j] * sum_{k<vlen} e[j][k] * values[b][k][v] ----
    const int v0 = tid * 2;
    const float* vb = values + (long long)b * K_ * V_ + v0;
    unsigned long long acc[QT] = {0ull, 0ull, 0ull, 0ull};
    int k = 0;
    #pragma unroll 1
    for (; k + 4 <= vlen; k += 4) {
        float2 vv0 = *(const float2*)(vb + (long long)(k + 0) * V_);
        float2 vv1 = *(const float2*)(vb + (long long)(k + 1) * V_);
        float2 vv2 = *(const float2*)(vb + (long long)(k + 2) * V_);
        float2 vv3 = *(const float2*)(vb + (long long)(k + 3) * V_);
        unsigned long long p0 = pack2(vv0.x, vv0.y);
        unsigned long long p1 = pack2(vv1.x, vv1.y);
        unsigned long long p2 = pack2(vv2.x, vv2.y);
        unsigned long long p3 = pack2(vv3.x, vv3.y);
        #pragma unroll
        for (int j = 0; j < QT; j++) {
            float e0 = s_sc[j][k], e1 = s_sc[j][k + 1];
            float e2 = s_sc[j][k + 2], e3 = s_sc[j][k + 3];
            acc[j] = fma2(pack2(e0, e0), p0, acc[j]);
            acc[j] = fma2(pack2(e1, e1), p1, acc[j]);
            acc[j] = fma2(pack2(e2, e2), p2, acc[j]);
            acc[j] = fma2(pack2(e3, e3), p3, acc[j]);
        }
    }
    for (; k < vlen; k++) {
        float2 vv = *(const float2*)(vb + (long long)k * V_);
        unsigned long long p = pack2(vv.x, vv.y);
        #pragma unroll
        for (int j = 0; j < QT; j++) {
            float e = s_sc[j][k];
            acc[j] = fma2(pack2(e, e), p, acc[j]);
        }
    }
    #pragma unroll
    for (int j = 0; j < QT; j++) {
        float2 r = unpack2(acc[j]);
        float2 o = make_float2(r.x * inv[j], r.y * inv[j]);
        *(float2*)(out + (long long)(b * Q_ + q0 + j) * V_ + v0) = o;
    }
}

// ----------------------------------------------------------------------------
extern "C" void kernel_launch(void* const* d_in, const int* in_sizes, int n_in,
                              void* d_out, int out_size)
{
    const float* queries = (const float*)d_in[0];  // [B,Q,D]
    const float* keys    = (const float*)d_in[1];  // [B,K,D]
    const float* values  = (const float*)d_in[2];  // [B,K,V]
    const int*   vlens   = (const int*)  d_in[3];  // [B]
    const float* Wq      = (const float*)d_in[4];  // [D,H]
    const float* Wk      = (const float*)d_in[5];  // [D,H]
    const float* wv      = (const float*)d_in[6];  // [H]
    float* out = (float*)d_out;                    // [B,Q,V]

    proj_gemm<<<dim3(H_ / 64, 16 + 128), 128>>>(queries, keys, Wq, Wk);
    fused_attn<<<dim3(Q_ / 4, B_), 256>>>(wv, vlens, values, out);
}

// round 4
// speedup vs baseline: 1.7077x; 1.7077x over previous
#include <cuda_runtime.h>
#include <cstdint>

constexpr int B_ = 8;     // batch
constexpr int Q_ = 128;   // queries
constexpr int K_ = 1024;  // keys
constexpr int D_ = 512;   // qk feature dim
constexpr int H_ = 256;   // hidden
constexpr int V_ = 512;   // value dim
constexpr int MK = B_ * K_;   // 8192 rows of kproj

// Scratch (no cudaMalloc allowed)
__device__ float g_qproj [B_ * Q_ * H_];   // [B*Q][H]   1 MB
__device__ float g_kprojT[H_ * B_ * K_];   // [H][B*K]   8 MB (transposed)
__device__ float g_scores[B_ * Q_ * K_];   // [B*Q][K]   4 MB

__device__ __forceinline__ float tanh_fast(float x) {
    float y;
    asm("tanh.approx.f32 %0, %1;" : "=f"(y) : "f"(x));
    return y;
}
__device__ __forceinline__ unsigned long long pack2(float lo, float hi) {
    unsigned long long r;
    asm("mov.b64 %0, {%1, %2};" : "=l"(r) : "f"(lo), "f"(hi));
    return r;
}
__device__ __forceinline__ float2 unpack2(unsigned long long v) {
    float2 r;
    asm("mov.b64 {%0, %1}, %2;" : "=f"(r.x), "=f"(r.y) : "l"(v));
    return r;
}
__device__ __forceinline__ unsigned long long fma2(unsigned long long a,
                                                   unsigned long long b,
                                                   unsigned long long c) {
    unsigned long long d;
    asm("fma.rn.f32x2 %0, %1, %2, %3;" : "=l"(d) : "l"(a), "l"(b), "l"(c));
    return d;
}
__device__ __forceinline__ unsigned long long add2(unsigned long long a,
                                                   unsigned long long b) {
    unsigned long long d;
    asm("add.rn.f32x2 %0, %1, %2;" : "=l"(d) : "l"(a), "l"(b));
    return d;
}

// ----------------------------------------------------------------------------
// K1: merged projection GEMM (unchanged — measured ~33us).
// ----------------------------------------------------------------------------
__global__ __launch_bounds__(128)
void proj_gemm(const float* __restrict__ queries, const float* __restrict__ keys,
               const float* __restrict__ Wq, const float* __restrict__ Wk)
{
    __shared__ float As[16][68];
    __shared__ float Bs[16][64];

    const int tid = threadIdx.x;
    const bool isQ = (blockIdx.y < 16);
    const float* A;
    const float* W;
    long long row0;
    if (isQ) { A = queries; W = Wq; row0 = (long long)blockIdx.y * 64; }
    else     { A = keys;    W = Wk; row0 = (long long)(blockIdx.y - 16) * 64; }
    const int col0 = blockIdx.x * 64;

    const int r0 = (tid >> 4) * 8;
    const int tn = (tid & 15) * 4;

    unsigned long long acc[8][2];
    #pragma unroll
    for (int i = 0; i < 8; i++) { acc[i][0] = 0ull; acc[i][1] = 0ull; }

    const int l0 = tid * 2;
    for (int kb = 0; kb < D_; kb += 16) {
        #pragma unroll
        for (int u = 0; u < 2; u++) {
            int l = l0 + u;
            int arow = l >> 2, ac4 = (l & 3) * 4;
            float4 av = *(const float4*)(A + (row0 + arow) * D_ + kb + ac4);
            As[ac4 + 0][arow] = av.x;
            As[ac4 + 1][arow] = av.y;
            As[ac4 + 2][arow] = av.z;
            As[ac4 + 3][arow] = av.w;
            int brow = l >> 4, bc4 = (l & 15) * 4;
            *(float4*)&Bs[brow][bc4] =
                *(const float4*)(W + (long long)(kb + brow) * H_ + col0 + bc4);
        }
        __syncthreads();

        #pragma unroll
        for (int kk = 0; kk < 16; kk++) {
            float4 alo = *(const float4*)&As[kk][r0];
            float4 ahi = *(const float4*)&As[kk][r0 + 4];
            float4 bq  = *(const float4*)&Bs[kk][tn];
            unsigned long long b01 = pack2(bq.x, bq.y);
            unsigned long long b23 = pack2(bq.z, bq.w);
            float a[8] = {alo.x, alo.y, alo.z, alo.w, ahi.x, ahi.y, ahi.z, ahi.w};
            #pragma unroll
            for (int ii = 0; ii < 8; ii++) {
                unsigned long long a2 = pack2(a[ii], a[ii]);
                acc[ii][0] = fma2(a2, b01, acc[ii][0]);
                acc[ii][1] = fma2(a2, b23, acc[ii][1]);
            }
        }
        __syncthreads();
    }

    if (isQ) {
        #pragma unroll
        for (int ii = 0; ii < 8; ii++) {
            float2 lo = unpack2(acc[ii][0]);
            float2 hi = unpack2(acc[ii][1]);
            float4 o = make_float4(lo.x, lo.y, hi.x, hi.y);
            *(float4*)(g_qproj + (row0 + r0 + ii) * H_ + col0 + tn) = o;
        }
    } else {
        float vals[8][4];
        #pragma unroll
        for (int ii = 0; ii < 8; ii++) {
            float2 lo = unpack2(acc[ii][0]);
            float2 hi = unpack2(acc[ii][1]);
            vals[ii][0] = lo.x; vals[ii][1] = lo.y;
            vals[ii][2] = hi.x; vals[ii][3] = hi.y;
        }
        #pragma unroll
        for (int jj = 0; jj < 4; jj++) {
            long long n = col0 + tn + jj;
            float4 o0 = make_float4(vals[0][jj], vals[1][jj], vals[2][jj], vals[3][jj]);
            float4 o1 = make_float4(vals[4][jj], vals[5][jj], vals[6][jj], vals[7][jj]);
            *(float4*)(g_kprojT + n * MK + row0 + r0)     = o0;
            *(float4*)(g_kprojT + n * MK + row0 + r0 + 4) = o1;
        }
    }
}

// ----------------------------------------------------------------------------
// K2: masked tanh-scores only. grid = (32 q-tiles, 4 k-chunks, 8 b).
// Block: 256 threads, thread owns k = kp*256+tid, computes 4 q scores.
// Double-buffered smem staging of kprojT [16h][256k] tiles, ONE bar/chunk.
// Inner loop h-unrolled x2 with f32x2 add/fma.
// ----------------------------------------------------------------------------
__global__ __launch_bounds__(256)
void scores_kernel(const float* __restrict__ wv, const int* __restrict__ vlens)
{
    constexpr int QT = 4;
    constexpr int HC = 16;                    // h per chunk
    constexpr int NCH = H_ / HC;              // 16 chunks
    __shared__ float s_tile[2][HC][256];      // 32 KB double buffer
    __shared__ float s_q[QT][H_];             // 4 KB
    __shared__ float s_wv[H_];                // 1 KB

    const int b   = blockIdx.z;
    const int kp  = blockIdx.y;
    const int q0  = blockIdx.x * QT;
    const int tid = threadIdx.x;
    const int vlen = vlens[b];
    if (kp * 256 >= vlen) return;             // uniform across block

    for (int i = tid; i < QT * H_; i += 256)
        s_q[i >> 8][i & 255] = g_qproj[(long long)(b * Q_ + q0 + (i >> 8)) * H_ + (i & 255)];
    for (int i = tid; i < H_; i += 256) s_wv[i] = wv[i];

    const float* kbase = g_kprojT + (long long)b * K_ + kp * 256;

    // prologue: stage chunk 0
    float4 rn[4];
    #pragma unroll
    for (int i = 0; i < 4; i++) {
        int idx = i * 256 + tid;
        int h = idx >> 6, c4 = (idx & 63) << 2;
        rn[i] = *(const float4*)(kbase + (long long)h * MK + c4);
    }
    #pragma unroll
    for (int i = 0; i < 4; i++) {
        int idx = i * 256 + tid;
        int h = idx >> 6, c4 = (idx & 63) << 2;
        *(float4*)&s_tile[0][h][c4] = rn[i];
    }
    __syncthreads();

    unsigned long long acc[QT] = {0ull, 0ull, 0ull, 0ull};

    for (int hc = 0; hc < NCH; hc++) {
        const int cur = hc & 1;
        // issue next chunk's loads before compute (latency overlap)
        if (hc + 1 < NCH) {
            #pragma unroll
            for (int i = 0; i < 4; i++) {
                int idx = i * 256 + tid;
                int h = idx >> 6, c4 = (idx & 63) << 2;
                rn[i] = *(const float4*)(kbase + (long long)((hc + 1) * HC + h) * MK + c4);
            }
        }
        const int hbase = hc * HC;
        #pragma unroll
        for (int hh = 0; hh < HC; hh += 2) {
            float kv0 = s_tile[cur][hh][tid];
            float kv1 = s_tile[cur][hh + 1][tid];
            unsigned long long kvp = pack2(kv0, kv1);
            float2 w2 = *(const float2*)&s_wv[hbase + hh];
            unsigned long long wvp = pack2(w2.x, w2.y);
            #pragma unroll
            for (int j = 0; j < QT; j++) {
                float2 q2 = *(const float2*)&s_q[j][hbase + hh];
                float2 sf = unpack2(add2(pack2(q2.x, q2.y), kvp));
                unsigned long long t = pack2(tanh_fast(sf.x), tanh_fast(sf.y));
                acc[j] = fma2(t, wvp, acc[j]);
            }
        }
        if (hc + 1 < NCH) {
            #pragma unroll
            for (int i = 0; i < 4; i++) {
                int idx = i * 256 + tid;
                int h = idx >> 6, c4 = (idx & 63) << 2;
                *(float4*)&s_tile[1 - cur][h][c4] = rn[i];
            }
            __syncthreads();
        }
    }

    const int k = kp * 256 + tid;
    if (k < vlen) {
        #pragma unroll
        for (int j = 0; j < QT; j++) {
            float2 r = unpack2(acc[j]);
            g_scores[(long long)(b * Q_ + q0 + j) * K_ + k] = r.x + r.y;
        }
    }
}

// ----------------------------------------------------------------------------
// K3: masked softmax + AV. grid = (32 q-tiles, 8 b), 256 threads.
// ----------------------------------------------------------------------------
__global__ __launch_bounds__(256)
void softmax_av(const int* __restrict__ vlens, const float* __restrict__ values,
                float* __restrict__ out)
{
    constexpr int QT = 4;
    __shared__ float s_sc[QT][K_];   // 16 KB
    __shared__ float s_red[8];

    const int b   = blockIdx.y;
    const int q0  = blockIdx.x * QT;
    const int tid = threadIdx.x;
    const int lane = tid & 31;
    const int wid  = tid >> 5;
    const int vlen = vlens[b];

    #pragma unroll
    for (int j = 0; j < QT; j++)
        for (int k = tid; k < vlen; k += 256)
            s_sc[j][k] = g_scores[(long long)(b * Q_ + q0 + j) * K_ + k];
    __syncthreads();

    float inv[QT];
    for (int j = 0; j < QT; j++) {
        float m = -3.4e38f;
        for (int k = tid; k < vlen; k += 256) m = fmaxf(m, s_sc[j][k]);
        #pragma unroll
        for (int off = 16; off; off >>= 1)
            m = fmaxf(m, __shfl_xor_sync(0xffffffffu, m, off));
        if (lane == 0) s_red[wid] = m;
        __syncthreads();
        float mm = s_red[0];
        #pragma unroll
        for (int w = 1; w < 8; w++) mm = fmaxf(mm, s_red[w]);
        __syncthreads();

        float s = 0.f;
        for (int k = tid; k < vlen; k += 256) {
            float e = __expf(s_sc[j][k] - mm);
            s_sc[j][k] = e;
            s += e;
        }
        #pragma unroll
        for (int off = 16; off; off >>= 1)
            s += __shfl_xor_sync(0xffffffffu, s, off);
        if (lane == 0) s_red[wid] = s;
        __syncthreads();
        float ssum = 0.f;
        #pragma unroll
        for (int w = 0; w < 8; w++) ssum += s_red[w];
        inv[j] = 1.0f / ssum;
        __syncthreads();
    }

    const int v0 = tid * 2;
    const float* vb = values + (long long)b * K_ * V_ + v0;
    unsigned long long acc[QT] = {0ull, 0ull, 0ull, 0ull};
    int k = 0;
    #pragma unroll 1
    for (; k + 4 <= vlen; k += 4) {
        float2 vv0 = *(const float2*)(vb + (long long)(k + 0) * V_);
        float2 vv1 = *(const float2*)(vb + (long long)(k + 1) * V_);
        float2 vv2 = *(const float2*)(vb + (long long)(k + 2) * V_);
        float2 vv3 = *(const float2*)(vb + (long long)(k + 3) * V_);
        unsigned long long p0 = pack2(vv0.x, vv0.y);
        unsigned long long p1 = pack2(vv1.x, vv1.y);
        unsigned long long p2 = pack2(vv2.x, vv2.y);
        unsigned long long p3 = pack2(vv3.x, vv3.y);
        #pragma unroll
        for (int j = 0; j < QT; j++) {
            float e0 = s_sc[j][k], e1 = s_sc[j][k + 1];
            float e2 = s_sc[j][k + 2], e3 = s_sc[j][k + 3];
            acc[j] = fma2(pack2(e0, e0), p0, acc[j]);
            acc[j] = fma2(pack2(e1, e1), p1, acc[j]);
            acc[j] = fma2(pack2(e2, e2), p2, acc[j]);
            acc[j] = fma2(pack2(e3, e3), p3, acc[j]);
        }
    }
    for (; k < vlen; k++) {
        float2 vv = *(const float2*)(vb + (long long)k * V_);
        unsigned long long p = pack2(vv.x, vv.y);
        #pragma unroll
        for (int j = 0; j < QT; j++) {
            float e = s_sc[j][k];
            acc[j] = fma2(pack2(e, e), p, acc[j]);
        }
    }
    #pragma unroll
    for (int j = 0; j < QT; j++) {
        float2 r = unpack2(acc[j]);
        float2 o = make_float2(r.x * inv[j], r.y * inv[j]);
        *(float2*)(out + (long long)(b * Q_ + q0 + j) * V_ + v0) = o;
    }
}

// ----------------------------------------------------------------------------
extern "C" void kernel_launch(void* const* d_in, const int* in_sizes, int n_in,
                              void* d_out, int out_size)
{
    const float* queries = (const float*)d_in[0];  // [B,Q,D]
    const float* keys    = (const float*)d_in[1];  // [B,K,D]
    const float* values  = (const float*)d_in[2];  // [B,K,V]
    const int*   vlens   = (const int*)  d_in[3];  // [B]
    const float* Wq      = (const float*)d_in[4];  // [D,H]
    const float* Wk      = (const float*)d_in[5];  // [D,H]
    const float* wv      = (const float*)d_in[6];  // [H]
    float* out = (float*)d_out;                    // [B,Q,V]

    proj_gemm<<<dim3(H_ / 64, 16 + 128), 128>>>(queries, keys, Wq, Wk);
    scores_kernel<<<dim3(Q_ / 4, K_ / 256, B_), 256>>>(wv, vlens);
    softmax_av<<<dim3(Q_ / 4, B_), 256>>>(vlens, values, out);
}

// round 5
// speedup vs baseline: 1.8155x; 1.0631x over previous
#include <cuda_runtime.h>
#include <cstdint>

constexpr int B_ = 8;     // batch
constexpr int Q_ = 128;   // queries
constexpr int K_ = 1024;  // keys
constexpr int D_ = 512;   // qk feature dim
constexpr int H_ = 256;   // hidden
constexpr int V_ = 512;   // value dim
constexpr int MK = B_ * K_;   // 8192 rows of kproj

// Scratch (no cudaMalloc allowed)
__device__ float g_qproj [B_ * Q_ * H_];   // [B*Q][H]   1 MB
__device__ float g_kprojT[H_ * B_ * K_];   // [H][B*K]   8 MB (transposed)
__device__ float g_scores[B_ * Q_ * K_];   // [B*Q][K]   4 MB

__device__ __forceinline__ float tanh_fast(float x) {
    float y;
    asm("tanh.approx.f32 %0, %1;" : "=f"(y) : "f"(x));
    return y;
}
__device__ __forceinline__ unsigned long long pack2(float lo, float hi) {
    unsigned long long r;
    asm("mov.b64 %0, {%1, %2};" : "=l"(r) : "f"(lo), "f"(hi));
    return r;
}
__device__ __forceinline__ float2 unpack2(unsigned long long v) {
    float2 r;
    asm("mov.b64 {%0, %1}, %2;" : "=f"(r.x), "=f"(r.y) : "l"(v));
    return r;
}
__device__ __forceinline__ unsigned long long fma2(unsigned long long a,
                                                   unsigned long long b,
                                                   unsigned long long c) {
    unsigned long long d;
    asm("fma.rn.f32x2 %0, %1, %2, %3;" : "=l"(d) : "l"(a), "l"(b), "l"(c));
    return d;
}
__device__ __forceinline__ unsigned long long add2(unsigned long long a,
                                                   unsigned long long b) {
    unsigned long long d;
    asm("add.rn.f32x2 %0, %1, %2;" : "=l"(d) : "l"(a), "l"(b));
    return d;
}

// ----------------------------------------------------------------------------
// K1: merged projection GEMM, now with:
//   - masked early-exit for kproj tiles with k0 >= vlen[b]
//   - double-buffered smem (one sync per BK step, LDG/FMA overlap)
// ----------------------------------------------------------------------------
__global__ __launch_bounds__(128)
void proj_gemm(const float* __restrict__ queries, const float* __restrict__ keys,
               const float* __restrict__ Wq, const float* __restrict__ Wk,
               const int* __restrict__ vlens)
{
    __shared__ float As[2][16][68];
    __shared__ float Bs[2][16][64];

    const int tid = threadIdx.x;
    const bool isQ = (blockIdx.y < 16);
    const float* A;
    const float* W;
    long long row0;
    if (isQ) {
        A = queries; W = Wq; row0 = (long long)blockIdx.y * 64;
    } else {
        int r  = (blockIdx.y - 16) * 64;
        int b  = r >> 10;           // /1024
        int k0 = r & 1023;
        if (k0 >= vlens[b]) return; // masked kproj tile: skip (uniform)
        A = keys; W = Wk; row0 = r;
    }
    const int col0 = blockIdx.x * 64;

    const int r0 = (tid >> 4) * 8;
    const int tn = (tid & 15) * 4;

    // loader lane mapping (2 float4 loads per thread per matrix)
    int arow[2], ac4[2], brow[2], bc4[2];
    #pragma unroll
    for (int u = 0; u < 2; u++) {
        int l = tid * 2 + u;
        arow[u] = l >> 2;  ac4[u] = (l & 3) << 2;
        brow[u] = l >> 4;  bc4[u] = (l & 15) << 2;
    }

    unsigned long long acc[8][2];
    #pragma unroll
    for (int i = 0; i < 8; i++) { acc[i][0] = 0ull; acc[i][1] = 0ull; }

    float4 avr[2], bvr[2];
    // prologue: load kb=0
    #pragma unroll
    for (int u = 0; u < 2; u++) {
        avr[u] = *(const float4*)(A + (row0 + arow[u]) * D_ + ac4[u]);
        bvr[u] = *(const float4*)(W + (long long)brow[u] * H_ + col0 + bc4[u]);
    }
    #pragma unroll
    for (int u = 0; u < 2; u++) {
        As[0][ac4[u] + 0][arow[u]] = avr[u].x;
        As[0][ac4[u] + 1][arow[u]] = avr[u].y;
        As[0][ac4[u] + 2][arow[u]] = avr[u].z;
        As[0][ac4[u] + 3][arow[u]] = avr[u].w;
        *(float4*)&Bs[0][brow[u]][bc4[u]] = bvr[u];
    }
    __syncthreads();

    constexpr int NKB = D_ / 16;   // 32
    for (int it = 0; it < NKB; it++) {
        const int cur = it & 1;
        if (it + 1 < NKB) {
            const int kb = (it + 1) * 16;
            #pragma unroll
            for (int u = 0; u < 2; u++) {
                avr[u] = *(const float4*)(A + (row0 + arow[u]) * D_ + kb + ac4[u]);
                bvr[u] = *(const float4*)(W + (long long)(kb + brow[u]) * H_ + col0 + bc4[u]);
            }
        }
        #pragma unroll
        for (int kk = 0; kk < 16; kk++) {
            float4 alo = *(const float4*)&As[cur][kk][r0];
            float4 ahi = *(const float4*)&As[cur][kk][r0 + 4];
            float4 bq  = *(const float4*)&Bs[cur][kk][tn];
            unsigned long long b01 = pack2(bq.x, bq.y);
            unsigned long long b23 = pack2(bq.z, bq.w);
            float a[8] = {alo.x, alo.y, alo.z, alo.w, ahi.x, ahi.y, ahi.z, ahi.w};
            #pragma unroll
            for (int ii = 0; ii < 8; ii++) {
                unsigned long long a2 = pack2(a[ii], a[ii]);
                acc[ii][0] = fma2(a2, b01, acc[ii][0]);
                acc[ii][1] = fma2(a2, b23, acc[ii][1]);
            }
        }
        if (it + 1 < NKB) {
            const int nxt = 1 - cur;
            #pragma unroll
            for (int u = 0; u < 2; u++) {
                As[nxt][ac4[u] + 0][arow[u]] = avr[u].x;
                As[nxt][ac4[u] + 1][arow[u]] = avr[u].y;
                As[nxt][ac4[u] + 2][arow[u]] = avr[u].z;
                As[nxt][ac4[u] + 3][arow[u]] = avr[u].w;
                *(float4*)&Bs[nxt][brow[u]][bc4[u]] = bvr[u];
            }
            __syncthreads();
        }
    }

    if (isQ) {
        #pragma unroll
        for (int ii = 0; ii < 8; ii++) {
            float2 lo = unpack2(acc[ii][0]);
            float2 hi = unpack2(acc[ii][1]);
            float4 o = make_float4(lo.x, lo.y, hi.x, hi.y);
            *(float4*)(g_qproj + (row0 + r0 + ii) * H_ + col0 + tn) = o;
        }
    } else {
        float vals[8][4];
        #pragma unroll
        for (int ii = 0; ii < 8; ii++) {
            float2 lo = unpack2(acc[ii][0]);
            float2 hi = unpack2(acc[ii][1]);
            vals[ii][0] = lo.x; vals[ii][1] = lo.y;
            vals[ii][2] = hi.x; vals[ii][3] = hi.y;
        }
        #pragma unroll
        for (int jj = 0; jj < 4; jj++) {
            long long n = col0 + tn + jj;
            float4 o0 = make_float4(vals[0][jj], vals[1][jj], vals[2][jj], vals[3][jj]);
            float4 o1 = make_float4(vals[4][jj], vals[5][jj], vals[6][jj], vals[7][jj]);
            *(float4*)(g_kprojT + n * MK + row0 + r0)     = o0;
            *(float4*)(g_kprojT + n * MK + row0 + r0 + 4) = o1;
        }
    }
}

// ----------------------------------------------------------------------------
// K2: masked tanh-scores (unchanged from round 4 — near MUFU floor).
// ----------------------------------------------------------------------------
__global__ __launch_bounds__(256)
void scores_kernel(const float* __restrict__ wv, const int* __restrict__ vlens)
{
    constexpr int QT = 4;
    constexpr int HC = 16;
    constexpr int NCH = H_ / HC;
    __shared__ float s_tile[2][HC][256];
    __shared__ float s_q[QT][H_];
    __shared__ float s_wv[H_];

    const int b   = blockIdx.z;
    const int kp  = blockIdx.y;
    const int q0  = blockIdx.x * QT;
    const int tid = threadIdx.x;
    const int vlen = vlens[b];
    if (kp * 256 >= vlen) return;

    for (int i = tid; i < QT * H_; i += 256)
        s_q[i >> 8][i & 255] = g_qproj[(long long)(b * Q_ + q0 + (i >> 8)) * H_ + (i & 255)];
    for (int i = tid; i < H_; i += 256) s_wv[i] = wv[i];

    const float* kbase = g_kprojT + (long long)b * K_ + kp * 256;

    float4 rn[4];
    #pragma unroll
    for (int i = 0; i < 4; i++) {
        int idx = i * 256 + tid;
        int h = idx >> 6, c4 = (idx & 63) << 2;
        rn[i] = *(const float4*)(kbase + (long long)h * MK + c4);
    }
    #pragma unroll
    for (int i = 0; i < 4; i++) {
        int idx = i * 256 + tid;
        int h = idx >> 6, c4 = (idx & 63) << 2;
        *(float4*)&s_tile[0][h][c4] = rn[i];
    }
    __syncthreads();

    unsigned long long acc[QT] = {0ull, 0ull, 0ull, 0ull};

    for (int hc = 0; hc < NCH; hc++) {
        const int cur = hc & 1;
        if (hc + 1 < NCH) {
            #pragma unroll
            for (int i = 0; i < 4; i++) {
                int idx = i * 256 + tid;
                int h = idx >> 6, c4 = (idx & 63) << 2;
                rn[i] = *(const float4*)(kbase + (long long)((hc + 1) * HC + h) * MK + c4);
            }
        }
        const int hbase = hc * HC;
        #pragma unroll
        for (int hh = 0; hh < HC; hh += 2) {
            float kv0 = s_tile[cur][hh][tid];
            float kv1 = s_tile[cur][hh + 1][tid];
            unsigned long long kvp = pack2(kv0, kv1);
            float2 w2 = *(const float2*)&s_wv[hbase + hh];
            unsigned long long wvp = pack2(w2.x, w2.y);
            #pragma unroll
            for (int j = 0; j < QT; j++) {
                float2 q2 = *(const float2*)&s_q[j][hbase + hh];
                float2 sf = unpack2(add2(pack2(q2.x, q2.y), kvp));
                unsigned long long t = pack2(tanh_fast(sf.x), tanh_fast(sf.y));
                acc[j] = fma2(t, wvp, acc[j]);
            }
        }
        if (hc + 1 < NCH) {
            #pragma unroll
            for (int i = 0; i < 4; i++) {
                int idx = i * 256 + tid;
                int h = idx >> 6, c4 = (idx & 63) << 2;
                *(float4*)&s_tile[1 - cur][h][c4] = rn[i];
            }
            __syncthreads();
        }
    }

    const int k = kp * 256 + tid;
    if (k < vlen) {
        #pragma unroll
        for (int j = 0; j < QT; j++) {
            float2 r = unpack2(acc[j]);
            g_scores[(long long)(b * Q_ + q0 + j) * K_ + k] = r.x + r.y;
        }
    }
}

// ----------------------------------------------------------------------------
// K3: masked softmax + AV. QT=8 (halves values re-read traffic), k-unroll 8.
// grid = (16 q-tiles, 8 b), 256 threads.
// ----------------------------------------------------------------------------
__global__ __launch_bounds__(256)
void softmax_av(const int* __restrict__ vlens, const float* __restrict__ values,
                float* __restrict__ out)
{
    constexpr int QT = 8;
    __shared__ float s_sc[QT][K_];   // 32 KB
    __shared__ float s_red[8];

    const int b   = blockIdx.y;
    const int q0  = blockIdx.x * QT;
    const int tid = threadIdx.x;
    const int lane = tid & 31;
    const int wid  = tid >> 5;
    const int vlen = vlens[b];

    #pragma unroll
    for (int j = 0; j < QT; j++)
        for (int k = tid; k < vlen; k += 256)
            s_sc[j][k] = g_scores[(long long)(b * Q_ + q0 + j) * K_ + k];
    __syncthreads();

    float inv[QT];
    #pragma unroll 1
    for (int j = 0; j < QT; j++) {
        float m = -3.4e38f;
        for (int k = tid; k < vlen; k += 256) m = fmaxf(m, s_sc[j][k]);
        #pragma unroll
        for (int off = 16; off; off >>= 1)
            m = fmaxf(m, __shfl_xor_sync(0xffffffffu, m, off));
        if (lane == 0) s_red[wid] = m;
        __syncthreads();
        float mm = s_red[0];
        #pragma unroll
        for (int w = 1; w < 8; w++) mm = fmaxf(mm, s_red[w]);
        __syncthreads();

        float s = 0.f;
        for (int k = tid; k < vlen; k += 256) {
            float e = __expf(s_sc[j][k] - mm);
            s_sc[j][k] = e;
            s += e;
        }
        #pragma unroll
        for (int off = 16; off; off >>= 1)
            s += __shfl_xor_sync(0xffffffffu, s, off);
        if (lane == 0) s_red[wid] = s;
        __syncthreads();
        float ssum = 0.f;
        #pragma unroll
        for (int w = 0; w < 8; w++) ssum += s_red[w];
        inv[j] = 1.0f / ssum;
        __syncthreads();
    }

    // AV: thread owns v-pair v0..v0+1; k unrolled x8 for MLP.
    const int v0 = tid * 2;
    const float* vb = values + (long long)b * K_ * V_ + v0;
    unsigned long long acc[QT];
    #pragma unroll
    for (int j = 0; j < QT; j++) acc[j] = 0ull;

    int k = 0;
    #pragma unroll 1
    for (; k + 8 <= vlen; k += 8) {
        unsigned long long p[8];
        #pragma unroll
        for (int t = 0; t < 8; t++) {
            float2 vv = *(const float2*)(vb + (long long)(k + t) * V_);
            p[t] = pack2(vv.x, vv.y);
        }
        #pragma unroll
        for (int j = 0; j < QT; j++) {
            #pragma unroll
            for (int t = 0; t < 8; t++) {
                float e = s_sc[j][k + t];
                acc[j] = fma2(pack2(e, e), p[t], acc[j]);
            }
        }
    }
    for (; k < vlen; k++) {
        float2 vv = *(const float2*)(vb + (long long)k * V_);
        unsigned long long p = pack2(vv.x, vv.y);
        #pragma unroll
        for (int j = 0; j < QT; j++) {
            float e = s_sc[j][k];
            acc[j] = fma2(pack2(e, e), p, acc[j]);
        }
    }
    #pragma unroll
    for (int j = 0; j < QT; j++) {
        float2 r = unpack2(acc[j]);
        float2 o = make_float2(r.x * inv[j], r.y * inv[j]);
        *(float2*)(out + (long long)(b * Q_ + q0 + j) * V_ + v0) = o;
    }
}

// ----------------------------------------------------------------------------
extern "C" void kernel_launch(void* const* d_in, const int* in_sizes, int n_in,
                              void* d_out, int out_size)
{
    const float* queries = (const float*)d_in[0];  // [B,Q,D]
    const float* keys    = (const float*)d_in[1];  // [B,K,D]
    const float* values  = (const float*)d_in[2];  // [B,K,V]
    const int*   vlens   = (const int*)  d_in[3];  // [B]
    const float* Wq      = (const float*)d_in[4];  // [D,H]
    const float* Wk      = (const float*)d_in[5];  // [D,H]
    const float* wv      = (const float*)d_in[6];  // [H]
    float* out = (float*)d_out;                    // [B,Q,V]

    proj_gemm<<<dim3(H_ / 64, 16 + 128), 128>>>(queries, keys, Wq, Wk, vlens);
    scores_kernel<<<dim3(Q_ / 4, K_ / 256, B_), 256>>>(wv, vlens);
    softmax_av<<<dim3(Q_ / 8, B_), 256>>>(vlens, values, out);
}